// round 14
// baseline (speedup 1.0000x reference)
#include <cuda_runtime.h>
#include <cstdint>
#include <cstddef>

// ============================================================================
// Problem: x(64,512,32,32) fp32, W(256,512,3,3), gamma/beta(256) -> out(64,256,32,32)
// Binarized 3x3 conv (pad 1) + batch BN + residual(x[:, :256]) + clip(-1,1)
// ============================================================================
#define BATCH   64
#define CIN     512
#define COUT    256
#define HW      32
#define NPIX    (HW*HW)          // 1024
#define BN_N    (BATCH*NPIX)     // 65536
#define XP      34               // padded spatial dim

// xb layout: [n][hp(34)][c4(4)][wp(34)][128] int8 (+1/-1), zero borders
#define XB_BYTES ((size_t)BATCH*XP*4*XP*128)       // 37,879,808
// wb layout: [kk(9)][co(256)][ci(512)] int8
#define WB_BYTES ((size_t)9*COUT*CIN)              // 1,179,648

__device__ __align__(128) int8_t g_xb[XB_BYTES];   // static zero-init => borders 0
__device__ __align__(128) int8_t g_wb[WB_BYTES];
__device__ __align__(128) int16_t g_conv[(size_t)BATCH*COUT*NPIX]; // exact ints, |v|<=4608
__device__ int                g_sum[COUT];
__device__ unsigned long long g_sumsq[COUT];

#define SWZ128(off) ((off) ^ (((off) >> 3) & 0x70))

__device__ __forceinline__ uint32_t smem_to_u32(const void* p) {
    uint32_t a;
    asm("{ .reg .u64 t; cvta.to.shared.u64 t, %1; cvt.u32.u64 %0, t; }" : "=r"(a) : "l"(p));
    return a;
}
__device__ __forceinline__ void cp_async16(uint32_t dst, const void* src) {
    asm volatile("cp.async.cg.shared.global [%0], [%1], 16;" :: "r"(dst), "l"(src) : "memory");
}
__device__ __forceinline__ void cp_commit() {
    asm volatile("cp.async.commit_group;" ::: "memory");
}
template<int N>
__device__ __forceinline__ void cp_wait() {
    asm volatile("cp.async.wait_group %0;" :: "n"(N) : "memory");
}
__device__ __forceinline__ void ldsm_x4(uint32_t& r0, uint32_t& r1, uint32_t& r2, uint32_t& r3,
                                        uint32_t addr) {
    asm volatile("ldmatrix.sync.aligned.m8n8.x4.shared.b16 {%0,%1,%2,%3}, [%4];"
        : "=r"(r0), "=r"(r1), "=r"(r2), "=r"(r3) : "r"(addr));
}
__device__ __forceinline__ void mma_s8(int* d, const uint32_t* a, const uint32_t* b) {
    asm volatile(
        "mma.sync.aligned.m16n8k32.row.col.s32.s8.s8.s32 "
        "{%0,%1,%2,%3}, {%4,%5,%6,%7}, {%8,%9}, {%0,%1,%2,%3};"
        : "+r"(d[0]), "+r"(d[1]), "+r"(d[2]), "+r"(d[3])
        : "r"(a[0]), "r"(a[1]), "r"(a[2]), "r"(a[3]), "r"(b[0]), "r"(b[1]));
}

// ============================================================================
// Fused prep:
//  blocks [0,1152): binarize W, 4 consecutive outputs per thread. Block 0
//                   zeroes stats.
//  blocks [1152,3200): binarize x -> padded chunked NHWC int8.
//    Single-barrier pipeline: all 64 global loads issued up front (MLP ~64),
//    packed to 4 uint4s in regs; staged to 16KB swizzled smem; ONE
//    __syncthreads; 4 contiguous 512B/warp global stores.
// ============================================================================
#define PREPW_BLOCKS 1152
#define PREP_BLOCKS  (PREPW_BLOCKS + 2048)

__global__ void prep_kernel(const float* __restrict__ W, const float* __restrict__ x) {
    __shared__ __align__(16) uint4 stage[4][256];
    if (blockIdx.x < PREPW_BLOCKS) {
        if (blockIdx.x == 0) {                        // fused zero_stats
            g_sum[threadIdx.x] = 0;
            g_sumsq[threadIdx.x] = 0ull;
        }
        int t_o = (blockIdx.x * 256 + threadIdx.x) * 4;   // 4 consecutive outputs
        uint8_t bytes[4];
        #pragma unroll
        for (int k = 0; k < 4; k++) {
            int o = t_o + k;
            int kk = o >> 17;                          // /131072
            int r  = o & 131071;
            int co = r >> 9;
            int ci = r & 511;
            float v = W[(size_t)(co * 512 + ci) * 9 + kk];
            bytes[k] = (v >= 0.0f) ? 0x01 : 0xFF;
        }
        *(uint32_t*)(g_wb + t_o) = *(const uint32_t*)bytes;
        return;
    }
    // ---- prep_x: one block per (n,h) ----
    int b = blockIdx.x - PREPW_BLOCKS;   // 0..2047
    int n = b >> 5, h = b & 31;
    int tx = threadIdx.x & 31;           // w   (load role)
    int ty = threadIdx.x >> 5;           // 16-channel group (load role)

    // Phase 1: all 64 loads in flight, pack as they land
    uint4 packed[4];
    #pragma unroll
    for (int c4 = 0; c4 < 4; c4++) {
        const float* src = x + ((size_t)(n * 512 + c4 * 128 + ty * 16)) * 1024 + h * 32 + tx;
        uint8_t bytes[16];
        #pragma unroll
        for (int j = 0; j < 16; j++) {
            float v = src[(size_t)j * 1024];          // next channel, same (h,w)
            bytes[j] = (v >= 0.0f) ? 0x01 : 0xFF;
        }
        packed[c4] = *(const uint4*)bytes;
    }

    // Phase 2: stage (swizzled), one barrier, contiguous stores
    #pragma unroll
    for (int c4 = 0; c4 < 4; c4++)
        stage[c4][tx * 8 + (ty ^ (tx & 7))] = packed[c4];
    __syncthreads();

    int w2 = threadIdx.x >> 3;           // w   (store role)
    int s2 = threadIdx.x & 7;            // 16B segment (store role)
    #pragma unroll
    for (int c4 = 0; c4 < 4; c4++) {
        uint4 v = stage[c4][w2 * 8 + (s2 ^ (w2 & 7))];
        uint8_t* dst = (uint8_t*)g_xb +
            (((size_t)(n * 34 + h + 1) * 4 + c4) * 34 + (w2 + 1)) * 128 + s2 * 16;
        *(uint4*)dst = v;                             // warp: 512B contiguous
    }
}

// ============================================================================
// Conv: implicit GEMM, mma.sync m16n8k32 s8. 2 CTAs/SM. (R8 config — best.)
// 3-stage cp.async pipeline: wait -> barrier -> issue(c+2) -> compute(c);
// chunks c+1 and c+2 in flight during compute(c).
// Grid: (512 px-tiles, 2 co-blocks). 256 threads = 8 warps (warp tile 64x32).
// ============================================================================
#define STAGE_BYTES 32768
#define STAT_OFF    (3 * STAGE_BYTES)            // 98304
#define CONV_SMEM   (STAT_OFF + 128*4 + 128*8)   // 99840

__global__ void __launch_bounds__(256, 2)
conv_kernel() {
    extern __shared__ __align__(1024) char smem[];
    uint32_t smem_base = smem_to_u32(smem);
    int* s_sum = (int*)(smem + STAT_OFF);
    unsigned long long* s_sq = (unsigned long long*)(smem + STAT_OFF + 512);

    const int tid = threadIdx.x;
    const int lane = tid & 31, wid = tid >> 5;
    const int warp_m = wid & 1, warp_n = wid >> 1;        // 2 x 4 warps
    const int pxt = blockIdx.x;                            // 0..511
    const int co_base = blockIdx.y * 128;
    const int n_img = pxt >> 3;
    const int hbase = (pxt & 7) * 4;                       // 4 output rows per tile

    if (tid < 128) { s_sum[tid] = 0; s_sq[tid] = 0ull; }

    // ---- async stage loader: 2048 x 16B per chunk, 8 per thread ----
    auto load_chunk = [&](int stage, int c) {
        int kk = c >> 2, c4 = c & 3;
        int kh = kk / 3, kw = kk - kh * 3;
        uint32_t sA = smem_base + stage * STAGE_BYTES;
        uint32_t sB = sA + 16384;
        const int8_t* wsrc = g_wb + (size_t)kk * 131072 + c4 * 128;
        #pragma unroll
        for (int j = 0; j < 8; j++) {
            int idx = tid + j * 256;
            if (idx < 1024) {                               // A: co x ci
                int row = idx >> 3, seg = idx & 7;
                const void* src = wsrc + (size_t)(co_base + row) * 512 + seg * 16;
                cp_async16(sA + SWZ128((uint32_t)row * 128 + seg * 16), src);
            } else {                                        // B: px x ci
                int bi = idx - 1024;
                int row = bi >> 3, seg = bi & 7;
                int hp = hbase + (row >> 5) + kh;
                int wp = (row & 31) + kw;
                const void* src = g_xb +
                    (((size_t)(n_img * 34 + hp) * 4 + c4) * 34 + wp) * 128 + seg * 16;
                cp_async16(sB + SWZ128((uint32_t)row * 128 + seg * 16), src);
            }
        }
        cp_commit();
    };

    // ---- per-thread ldmatrix address patterns ----
    const int q = lane >> 3, r8 = lane & 7;
    const int a_row0 = (q & 1) * 8 + r8;
    const int a_colh = (q >> 1) * 16;
    const int b_row0 = warp_n * 32 + (q >> 1) * 8 + r8;
    const int b_colh = (q & 1) * 16;

    int acc[4][4][4];
    #pragma unroll
    for (int i = 0; i < 4; i++)
        #pragma unroll
        for (int j = 0; j < 4; j++)
            #pragma unroll
            for (int k = 0; k < 4; k++) acc[i][j][k] = 0;

    load_chunk(0, 0);
    load_chunk(1, 1);

    int cur = 0, nst = 2;
    for (int c = 0; c < 36; c++) {
        // chunk c complete (chunk c+1 may still be in flight)
        if (c == 35) cp_wait<0>(); else cp_wait<1>();
        __syncthreads();   // visibility of all threads' async writes; stage nst free
        if (c + 2 < 36) load_chunk(nst, c + 2);

        uint32_t sA = smem_base + cur * STAGE_BYTES + warp_m * (64 * 128);
        uint32_t sB = smem_base + cur * STAGE_BYTES + 16384;

        #pragma unroll
        for (int ks = 0; ks < 4; ks++) {
            uint32_t af[4][4];
            #pragma unroll
            for (int mf = 0; mf < 4; mf++) {
                int row = mf * 16 + a_row0;
                int col = ks * 32 + a_colh;
                uint32_t off = (uint32_t)row * 128 + (col ^ ((row & 7) << 4));
                ldsm_x4(af[mf][0], af[mf][1], af[mf][2], af[mf][3], sA + off);
            }
            uint32_t bf[4][2];
            #pragma unroll
            for (int nfp = 0; nfp < 2; nfp++) {
                int row = b_row0 + nfp * 16;
                int col = ks * 32 + b_colh;
                uint32_t off = (uint32_t)row * 128 + (col ^ ((row & 7) << 4));
                ldsm_x4(bf[nfp*2][0], bf[nfp*2][1], bf[nfp*2+1][0], bf[nfp*2+1][1], sB + off);
            }
            #pragma unroll
            for (int mf = 0; mf < 4; mf++)
                #pragma unroll
                for (int nf = 0; nf < 4; nf++)
                    mma_s8(acc[mf][nf], af[mf], bf[nf]);
        }

        cur = (cur == 2) ? 0 : cur + 1;
        nst = (nst == 2) ? 0 : nst + 1;
    }

    // ---- epilogue: write int16 conv scratch (NCHW) + exact-int stats ----
    const int g = lane >> 2, t4 = lane & 3;
    #pragma unroll
    for (int mf = 0; mf < 4; mf++) {
        int coA = warp_m * 64 + mf * 16 + g;      // local channel (0..127)
        int coB = coA + 8;
        int sumA = 0, sumB = 0;
        long long sqA = 0, sqB = 0;
        #pragma unroll
        for (int nf = 0; nf < 4; nf++) {
            int c0 = acc[mf][nf][0], c1 = acc[mf][nf][1];
            int c2 = acc[mf][nf][2], c3 = acc[mf][nf][3];
            sumA += c0 + c1;  sqA += (long long)c0*c0 + (long long)c1*c1;
            sumB += c2 + c3;  sqB += (long long)c2*c2 + (long long)c3*c3;
            int px = pxt * 128 + warp_n * 32 + nf * 8 + 2 * t4;
            int pix = px & 1023;
            short2 vA = make_short2((short)c0, (short)c1);
            short2 vB = make_short2((short)c2, (short)c3);
            *(short2*)(g_conv + (((size_t)n_img * 256 + co_base + coA) << 10) + pix) = vA;
            *(short2*)(g_conv + (((size_t)n_img * 256 + co_base + coB) << 10) + pix) = vB;
        }
        atomicAdd(&s_sum[coA], sumA);
        atomicAdd(&s_sum[coB], sumB);
        atomicAdd(&s_sq[coA], (unsigned long long)sqA);
        atomicAdd(&s_sq[coB], (unsigned long long)sqB);
    }
    __syncthreads();
    if (tid < 128) {
        atomicAdd(&g_sum[co_base + tid], s_sum[tid]);
        atomicAdd(&g_sumsq[co_base + tid], s_sq[tid]);
    }
}

// ============================================================================
// Apply (fused BN-param computation): per-thread fp32 scale/shift from exact
// integer stats. var = E[x^2] - m^2 (no cancellation: m^2 << E[x^2]).
// out = clip(conv*scale + shift + residual, -1, 1)
// ============================================================================
__global__ void apply_kernel(const float* __restrict__ x,
                             const float* __restrict__ gamma,
                             const float* __restrict__ beta,
                             float* __restrict__ out) {
    size_t i4 = (size_t)blockIdx.x * 256 + threadIdx.x;    // 4,194,304 groups of 4
    int n = (int)(i4 >> 16);
    int c = (int)((i4 >> 8) & 255);

    const float inv_n = 1.0f / 65536.0f;
    float m  = (float)g_sum[c] * inv_n;
    float e2 = (float)g_sumsq[c] * inv_n;
    float sc = gamma[c] * rsqrtf(e2 - m * m + 1e-5f);
    float sh = beta[c] - m * sc;

    short4 cv = *(const short4*)(g_conv + i4 * 4);
    const float4 rv = *(const float4*)(x + (((size_t)(n * 512 + c)) << 10) + ((i4 & 255) << 2));
    float4 o;
    o.x = fminf(1.0f, fmaxf(-1.0f, (float)cv.x * sc + sh + rv.x));
    o.y = fminf(1.0f, fmaxf(-1.0f, (float)cv.y * sc + sh + rv.y));
    o.z = fminf(1.0f, fmaxf(-1.0f, (float)cv.z * sc + sh + rv.z));
    o.w = fminf(1.0f, fmaxf(-1.0f, (float)cv.w * sc + sh + rv.w));
    *(float4*)(out + i4 * 4) = o;
}

// ============================================================================
// Launch: 3 kernels (prep fused; zero_stats in prep; bn_params in apply)
// ============================================================================
extern "C" void kernel_launch(void* const* d_in, const int* in_sizes, int n_in,
                              void* d_out, int out_size) {
    const float* x     = (const float*)d_in[0];
    const float* W     = (const float*)d_in[1];
    const float* gamma = (const float*)d_in[2];
    const float* beta  = (const float*)d_in[3];
    float* out = (float*)d_out;

    cudaFuncSetAttribute(conv_kernel, cudaFuncAttributeMaxDynamicSharedMemorySize, CONV_SMEM);

    prep_kernel<<<PREP_BLOCKS, 256>>>(W, x);
    conv_kernel<<<dim3(512, 2), 256, CONV_SMEM>>>();
    apply_kernel<<<16384, 256>>>(x, gamma, beta, out);
}

// round 16
// speedup vs baseline: 1.0384x; 1.0384x over previous
#include <cuda_runtime.h>
#include <cstdint>
#include <cstddef>

// ============================================================================
// Problem: x(64,512,32,32) fp32, W(256,512,3,3), gamma/beta(256) -> out(64,256,32,32)
// Binarized 3x3 conv (pad 1) + batch BN + residual(x[:, :256]) + clip(-1,1)
// ============================================================================
#define BATCH   64
#define CIN     512
#define COUT    256
#define HW      32
#define NPIX    (HW*HW)          // 1024
#define BN_N    (BATCH*NPIX)     // 65536
#define XP      34               // padded spatial dim

// xb layout: [n][hp(34)][c4(4)][wp(34)][128] int8 (+1/-1), zero borders
#define XB_BYTES ((size_t)BATCH*XP*4*XP*128)       // 37,879,808
// wb layout: [kk(9)][co(256)][ci(512)] int8
#define WB_BYTES ((size_t)9*COUT*CIN)              // 1,179,648

__device__ __align__(128) int8_t g_xb[XB_BYTES];   // static zero-init => borders 0
__device__ __align__(128) int8_t g_wb[WB_BYTES];
__device__ __align__(128) int16_t g_conv[(size_t)BATCH*COUT*NPIX]; // exact ints, |v|<=4608
__device__ int                g_sum[COUT];
__device__ unsigned long long g_sumsq[COUT];

#define SWZ128(off) ((off) ^ (((off) >> 3) & 0x70))

__device__ __forceinline__ uint32_t smem_to_u32(const void* p) {
    uint32_t a;
    asm("{ .reg .u64 t; cvta.to.shared.u64 t, %1; cvt.u32.u64 %0, t; }" : "=r"(a) : "l"(p));
    return a;
}
__device__ __forceinline__ void cp_async16(uint32_t dst, const void* src) {
    asm volatile("cp.async.cg.shared.global [%0], [%1], 16;" :: "r"(dst), "l"(src) : "memory");
}
__device__ __forceinline__ void cp_commit() {
    asm volatile("cp.async.commit_group;" ::: "memory");
}
template<int N>
__device__ __forceinline__ void cp_wait() {
    asm volatile("cp.async.wait_group %0;" :: "n"(N) : "memory");
}
__device__ __forceinline__ void ldsm_x4(uint32_t& r0, uint32_t& r1, uint32_t& r2, uint32_t& r3,
                                        uint32_t addr) {
    asm volatile("ldmatrix.sync.aligned.m8n8.x4.shared.b16 {%0,%1,%2,%3}, [%4];"
        : "=r"(r0), "=r"(r1), "=r"(r2), "=r"(r3) : "r"(addr));
}
__device__ __forceinline__ void mma_s8(int* d, const uint32_t* a, const uint32_t* b) {
    asm volatile(
        "mma.sync.aligned.m16n8k32.row.col.s32.s8.s8.s32 "
        "{%0,%1,%2,%3}, {%4,%5,%6,%7}, {%8,%9}, {%0,%1,%2,%3};"
        : "+r"(d[0]), "+r"(d[1]), "+r"(d[2]), "+r"(d[3])
        : "r"(a[0]), "r"(a[1]), "r"(a[2]), "r"(a[3]), "r"(b[0]), "r"(b[1]));
}

// ============================================================================
// Fused prep (R13 version — best measured):
//  blocks [0,1152): binarize W, 4 consecutive outputs/thread; block 0 zeroes stats.
//  blocks [1152,3200): binarize x -> padded chunked NHWC int8 via 4KB swizzled
//    smem stage so warp stores are 512B contiguous.
// ============================================================================
#define PREPW_BLOCKS 1152
#define PREP_BLOCKS  (PREPW_BLOCKS + 2048)

__global__ void prep_kernel(const float* __restrict__ W, const float* __restrict__ x) {
    __shared__ __align__(16) uint4 stage[256];
    if (blockIdx.x < PREPW_BLOCKS) {
        if (blockIdx.x == 0) {
            g_sum[threadIdx.x] = 0;
            g_sumsq[threadIdx.x] = 0ull;
        }
        int t_o = (blockIdx.x * 256 + threadIdx.x) * 4;
        uint8_t bytes[4];
        #pragma unroll
        for (int k = 0; k < 4; k++) {
            int o = t_o + k;
            int kk = o >> 17;
            int r  = o & 131071;
            int co = r >> 9;
            int ci = r & 511;
            float v = W[(size_t)(co * 512 + ci) * 9 + kk];
            bytes[k] = (v >= 0.0f) ? 0x01 : 0xFF;
        }
        *(uint32_t*)(g_wb + t_o) = *(const uint32_t*)bytes;
        return;
    }
    int b = blockIdx.x - PREPW_BLOCKS;   // 0..2047
    int n = b >> 5, h = b & 31;
    int tx = threadIdx.x & 31;           // w   (load role)
    int ty = threadIdx.x >> 5;           // 16-channel group (load role)
    int w2 = threadIdx.x >> 3;           // w   (store role)
    int s2 = threadIdx.x & 7;            // 16B segment (store role)

    for (int c4 = 0; c4 < 4; c4++) {
        const float* src = x + ((size_t)(n * 512 + c4 * 128 + ty * 16)) * 1024 + h * 32 + tx;
        uint8_t bytes[16];
        #pragma unroll
        for (int j = 0; j < 16; j++) {
            float v = src[(size_t)j * 1024];
            bytes[j] = (v >= 0.0f) ? 0x01 : 0xFF;
        }
        stage[tx * 8 + (ty ^ (tx & 7))] = *(const uint4*)bytes;
        __syncthreads();
        uint4 v = stage[w2 * 8 + (s2 ^ (w2 & 7))];
        uint8_t* dst = (uint8_t*)g_xb +
            (((size_t)(n * 34 + h + 1) * 4 + c4) * 34 + (w2 + 1)) * 128 + s2 * 16;
        *(uint4*)dst = v;
        __syncthreads();
    }
}

// ============================================================================
// Conv: implicit GEMM, mma.sync m16n8k32 s8. 2 CTAs/SM.
// Activation WINDOW in smem. Loop c4 outer, kk(tap) inner. The 6x34-row
// window (26112B) per c4 is loaded ONCE (double-buffered); B fragments are
// ldmatrix'd straight out of it with per-lane (kh,kw)-shifted addresses.
// A tiles (16KB/tap) use a 3-stage rotation, one cp group per iter; window
// slices for c4+1 ride in the groups of iters (c4, kk=0..7), so the
// wait<1> invariant also proves window residency.
// Grid: (512 px-tiles, 2 co-blocks). 256 threads = 8 warps (warp tile 64x32).
// ============================================================================
#define A_STAGE    16384
#define WROW_BYTES 4352                       // 34 wp x 128
#define WBUF_BYTES 26112                      // 6 rows
#define WBUF_OFF   (3 * A_STAGE)              // 49152
#define STAT_OFF   (WBUF_OFF + 2 * WBUF_BYTES)   // 101376
#define CONV_SMEM  (STAT_OFF + 128*4 + 128*8)    // 102912

__global__ void __launch_bounds__(256, 2)
conv_kernel() {
    extern __shared__ __align__(1024) char smem[];
    uint32_t smem_base = smem_to_u32(smem);
    int* s_sum = (int*)(smem + STAT_OFF);
    unsigned long long* s_sq = (unsigned long long*)(smem + STAT_OFF + 512);

    const int tid = threadIdx.x;
    const int lane = tid & 31, wid = tid >> 5;
    const int warp_m = wid & 1, warp_n = wid >> 1;        // 2 x 4 warps
    const int pxt = blockIdx.x;                            // 0..511
    const int co_base = blockIdx.y * 128;
    const int n_img = pxt >> 3;
    const int hbase = (pxt & 7) * 4;                       // 4 output rows per tile

    if (tid < 128) { s_sum[tid] = 0; s_sq[tid] = 0ull; }

    // ---- A tile loader: 1024 x 16B, 4 per thread ----
    auto load_A = [&](int stage, int c) {
        int c4 = c / 9, kk = c - c4 * 9;
        uint32_t sA = smem_base + stage * A_STAGE;
        const int8_t* wsrc = g_wb + (size_t)kk * 131072 + c4 * 128;
        #pragma unroll
        for (int j = 0; j < 4; j++) {
            int idx = tid + j * 256;                       // 0..1023
            int row = idx >> 3, seg = idx & 7;
            const void* src = wsrc + (size_t)(co_base + row) * 512 + seg * 16;
            cp_async16(sA + SWZ128((uint32_t)row * 128 + seg * 16), src);
        }
    };
    // ---- window slice loader: 204 units of 16B (slice s of 8) ----
    auto load_wslice = [&](int buf, int c4w, int s) {
        int u = s * 204 + tid;
        if (tid < 204) {
            int r = u / 272, rem = u - r * 272;
            int wp = rem >> 3, seg = rem & 7;
            uint32_t dst = smem_base + WBUF_OFF + buf * WBUF_BYTES
                         + (uint32_t)r * WROW_BYTES + wp * 128
                         + ((seg * 16) ^ ((wp & 7) << 4));
            const void* src = g_xb +
                (((size_t)(n_img * 34 + hbase + r) * 4 + c4w) * 34 + wp) * 128 + seg * 16;
            cp_async16(dst, src);
        }
    };
    // ---- full window load (prologue): 1632 units ----
    auto load_wfull = [&](int buf, int c4w) {
        #pragma unroll
        for (int j = 0; j < 7; j++) {
            int u = tid + j * 256;
            if (u < 1632) {
                int r = u / 272, rem = u - r * 272;
                int wp = rem >> 3, seg = rem & 7;
                uint32_t dst = smem_base + WBUF_OFF + buf * WBUF_BYTES
                             + (uint32_t)r * WROW_BYTES + wp * 128
                             + ((seg * 16) ^ ((wp & 7) << 4));
                const void* src = g_xb +
                    (((size_t)(n_img * 34 + hbase + r) * 4 + c4w) * 34 + wp) * 128 + seg * 16;
                cp_async16(dst, src);
            }
        }
    };

    // ---- per-thread ldmatrix address roles ----
    const int q = lane >> 3, r8 = lane & 7;
    const int a_row0 = (q & 1) * 8 + r8;
    const int a_colh = (q >> 1) * 16;
    const int w0 = (q >> 1) * 8 + r8;       // B row's w for nfp=0 (0..15)
    const int b_colh = (q & 1) * 16;

    int acc[4][4][4];
    #pragma unroll
    for (int i = 0; i < 4; i++)
        #pragma unroll
        for (int j = 0; j < 4; j++)
            #pragma unroll
            for (int k = 0; k < 4; k++) acc[i][j][k] = 0;

    // Prologue: window(c4=0) as group 0; A(chunk0), A(chunk1) as groups 1,2
    load_wfull(0, 0); cp_commit();
    load_A(0, 0);     cp_commit();
    load_A(1, 1);     cp_commit();

    int cur = 0, nst = 2;
    for (int c = 0; c < 36; c++) {
        if (c == 35) cp_wait<0>(); else cp_wait<1>();
        __syncthreads();   // all async writes visible; A stage nst + window buf free

        int c4 = c / 9, kk = c - c4 * 9;
        bool any = false;
        if (c + 2 < 36) { load_A(nst, c + 2); any = true; }
        if (c4 < 3 && kk < 8) { load_wslice((c4 + 1) & 1, c4 + 1, kk); any = true; }
        if (any) cp_commit();

        int kh = kk / 3, kw = kk - kh * 3;
        uint32_t sA = smem_base + cur * A_STAGE + warp_m * (64 * 128);
        uint32_t wrow = smem_base + WBUF_OFF + (c4 & 1) * WBUF_BYTES
                      + (uint32_t)(warp_n + kh) * WROW_BYTES;
        int wp0 = w0 + kw, wp1 = wp0 + 16;
        uint32_t b0 = wrow + wp0 * 128, sw0 = (uint32_t)(wp0 & 7) << 4;
        uint32_t b1 = wrow + wp1 * 128, sw1 = (uint32_t)(wp1 & 7) << 4;

        #pragma unroll
        for (int ks = 0; ks < 4; ks++) {
            uint32_t af[4][4];
            #pragma unroll
            for (int mf = 0; mf < 4; mf++) {
                int row = mf * 16 + a_row0;
                int col = ks * 32 + a_colh;
                uint32_t off = (uint32_t)row * 128 + (col ^ ((row & 7) << 4));
                ldsm_x4(af[mf][0], af[mf][1], af[mf][2], af[mf][3], sA + off);
            }
            uint32_t bf[4][2];
            uint32_t col = (uint32_t)(ks * 32 + b_colh);
            ldsm_x4(bf[0][0], bf[0][1], bf[1][0], bf[1][1], b0 + (col ^ sw0));
            ldsm_x4(bf[2][0], bf[2][1], bf[3][0], bf[3][1], b1 + (col ^ sw1));
            #pragma unroll
            for (int mf = 0; mf < 4; mf++)
                #pragma unroll
                for (int nf = 0; nf < 4; nf++)
                    mma_s8(acc[mf][nf], af[mf], bf[nf]);
        }

        cur = (cur == 2) ? 0 : cur + 1;
        nst = (nst == 2) ? 0 : nst + 1;
    }

    // ---- epilogue: write int16 conv scratch (NCHW) + exact-int stats ----
    const int g = lane >> 2, t4 = lane & 3;
    #pragma unroll
    for (int mf = 0; mf < 4; mf++) {
        int coA = warp_m * 64 + mf * 16 + g;      // local channel (0..127)
        int coB = coA + 8;
        int sumA = 0, sumB = 0;
        long long sqA = 0, sqB = 0;
        #pragma unroll
        for (int nf = 0; nf < 4; nf++) {
            int c0 = acc[mf][nf][0], c1 = acc[mf][nf][1];
            int c2 = acc[mf][nf][2], c3 = acc[mf][nf][3];
            sumA += c0 + c1;  sqA += (long long)c0*c0 + (long long)c1*c1;
            sumB += c2 + c3;  sqB += (long long)c2*c2 + (long long)c3*c3;
            int px = pxt * 128 + warp_n * 32 + nf * 8 + 2 * t4;
            int pix = px & 1023;
            short2 vA = make_short2((short)c0, (short)c1);
            short2 vB = make_short2((short)c2, (short)c3);
            *(short2*)(g_conv + (((size_t)n_img * 256 + co_base + coA) << 10) + pix) = vA;
            *(short2*)(g_conv + (((size_t)n_img * 256 + co_base + coB) << 10) + pix) = vB;
        }
        atomicAdd(&s_sum[coA], sumA);
        atomicAdd(&s_sum[coB], sumB);
        atomicAdd(&s_sq[coA], (unsigned long long)sqA);
        atomicAdd(&s_sq[coB], (unsigned long long)sqB);
    }
    __syncthreads();
    if (tid < 128) {
        atomicAdd(&g_sum[co_base + tid], s_sum[tid]);
        atomicAdd(&g_sumsq[co_base + tid], s_sq[tid]);
    }
}

// ============================================================================
// Apply (fused BN-param computation): per-thread fp32 scale/shift from exact
// integer stats. out = clip(conv*scale + shift + residual, -1, 1)
// ============================================================================
__global__ void apply_kernel(const float* __restrict__ x,
                             const float* __restrict__ gamma,
                             const float* __restrict__ beta,
                             float* __restrict__ out) {
    size_t i4 = (size_t)blockIdx.x * 256 + threadIdx.x;    // 4,194,304 groups of 4
    int n = (int)(i4 >> 16);
    int c = (int)((i4 >> 8) & 255);

    const float inv_n = 1.0f / 65536.0f;
    float m  = (float)g_sum[c] * inv_n;
    float e2 = (float)g_sumsq[c] * inv_n;
    float sc = gamma[c] * rsqrtf(e2 - m * m + 1e-5f);
    float sh = beta[c] - m * sc;

    short4 cv = *(const short4*)(g_conv + i4 * 4);
    const float4 rv = *(const float4*)(x + (((size_t)(n * 512 + c)) << 10) + ((i4 & 255) << 2));
    float4 o;
    o.x = fminf(1.0f, fmaxf(-1.0f, (float)cv.x * sc + sh + rv.x));
    o.y = fminf(1.0f, fmaxf(-1.0f, (float)cv.y * sc + sh + rv.y));
    o.z = fminf(1.0f, fmaxf(-1.0f, (float)cv.z * sc + sh + rv.z));
    o.w = fminf(1.0f, fmaxf(-1.0f, (float)cv.w * sc + sh + rv.w));
    *(float4*)(out + i4 * 4) = o;
}

// ============================================================================
// Launch: 3 kernels
// ============================================================================
extern "C" void kernel_launch(void* const* d_in, const int* in_sizes, int n_in,
                              void* d_out, int out_size) {
    const float* x     = (const float*)d_in[0];
    const float* W     = (const float*)d_in[1];
    const float* gamma = (const float*)d_in[2];
    const float* beta  = (const float*)d_in[3];
    float* out = (float*)d_out;

    cudaFuncSetAttribute(conv_kernel, cudaFuncAttributeMaxDynamicSharedMemorySize, CONV_SMEM);

    prep_kernel<<<PREP_BLOCKS, 256>>>(W, x);
    conv_kernel<<<dim3(512, 2), 256, CONV_SMEM>>>();
    apply_kernel<<<16384, 256>>>(x, gamma, beta, out);
}